// round 6
// baseline (speedup 1.0000x reference)
#include <cuda_runtime.h>
#include <cuda_fp16.h>
#include <cstdint>

// Problem constants
#define M_DIM   32
#define K_DIM   8192
#define N_DIM   8192
#define GROUP   128

#define NTILE   256                    // n-columns per CTA
#define SPLITS  16                     // split-K factor
#define KSPLIT  (K_DIM / SPLITS)       // 512 k per CTA
#define NUM_KT  (KSPLIT / GROUP)       // 4 k-tiles of 128
#define THREADS 256                    // 8 warps, each owns 32 n-columns
#define NTILES  (N_DIM / NTILE)        // 32

// Dynamic SMEM layout (bytes):
//  A fp16:  [32 m][APITCH halves], pitch 520 -> conflict-free b-frag LDS
//           (row stride 1040 B == 16 B mod 128 -> banks 4*lane4+(lane&3) unique)
//  k within each octet stored PERMUTED: (k0,k4,k1,k5,k2,k6,k3,k7)
#define APITCH  520
#define A_BYTES (M_DIM * APITCH * 2)   // 33280
#define W_OFF   A_BYTES
#define W_TILE  16384                  // 16 k-rows x 256 cols x int32
#define S_OFF   (W_OFF + 2 * W_TILE)   // 66048
#define S_TILE  1024                   // 256 fp32 scales
#define SMEM_TOTAL (S_OFF + 2 * S_TILE)  // 68096

// Split-K partials + completion counters (static device scratch)
__device__ float    g_partial[SPLITS * M_DIM * N_DIM];
__device__ unsigned g_ctr[NTILES];

static __device__ __forceinline__ uint32_t lop3_and_or(uint32_t a, uint32_t b, uint32_t c) {
    uint32_t d;
    asm("lop3.b32 %0, %1, %2, %3, 0xEA;" : "=r"(d) : "r"(a), "r"(b), "r"(c));
    return d;
}

static __device__ __forceinline__ void cpasync16(uint32_t dst, const void* src) {
    asm volatile("cp.async.cg.shared.global [%0], [%1], 16;\n" :: "r"(dst), "l"(src));
}
#define CP_COMMIT() asm volatile("cp.async.commit_group;\n" ::: "memory")
#define CP_WAIT(N)  asm volatile("cp.async.wait_group %0;\n" :: "n"(N) : "memory")

// Uniform per-lane dequant: lane j = lane&3 extracts nibble pair (j, j+4) of qword.
//  j even: u = q >> ((lane&2)*4); h = (u & 0x000F000F) | 0x64006400 -> (1024+n_j, 1024+n_j+4)
//          v = h*1 + (-1032) = n-8 (exact)
//  j odd:  h = (u & 0x00F000F0) | 0x64006400 -> (1024+16n, ...)
//          v = h*(1/16) + (-72) = n-8 (exact)
// then r = v * s (one fp16 rounding).
static __device__ __forceinline__ uint32_t dq2(uint32_t q, uint32_t sh, uint32_t mask,
                                               uint32_t cm2, uint32_t ca2, uint32_t s2) {
    uint32_t u = q >> sh;
    uint32_t h = lop3_and_or(u, mask, 0x64006400u);
    half2 v = __hfma2(*reinterpret_cast<half2*>(&h),
                      *reinterpret_cast<half2*>(&cm2),
                      *reinterpret_cast<half2*>(&ca2));
    half2 r = __hmul2(v, *reinterpret_cast<half2*>(&s2));
    return *reinterpret_cast<uint32_t*>(&r);
}

static __device__ __forceinline__ void mma_16816(float& d0, float& d1, float& d2, float& d3,
                                                 uint32_t a0, uint32_t a1, uint32_t a2,
                                                 uint32_t a3, uint32_t b0, uint32_t b1) {
    asm volatile(
        "mma.sync.aligned.m16n8k16.row.col.f32.f16.f16.f32 "
        "{%0,%1,%2,%3}, {%4,%5,%6,%7}, {%8,%9}, {%0,%1,%2,%3};\n"
        : "+f"(d0), "+f"(d1), "+f"(d2), "+f"(d3)
        : "r"(a0), "r"(a1), "r"(a2), "r"(a3), "r"(b0), "r"(b1));
}

__global__ void __launch_bounds__(THREADS, 3)
marlin_w4a16_fused(const float* __restrict__ A, const int* __restrict__ qw,
                   const float* __restrict__ scales, const float* __restrict__ bias,
                   float* __restrict__ out) {
    extern __shared__ __align__(16) char smem[];
    __shared__ unsigned s_old;

    half* a_sm = reinterpret_cast<half*>(smem);
    const uint32_t smem_u32 = (uint32_t)__cvta_generic_to_shared(smem);

    const int tid   = threadIdx.x;
    const int lane  = tid & 31;
    const int warp  = tid >> 5;            // 0..7
    const int lane4 = lane >> 2;           // 0..7

    // per-lane dequant constants
    const uint32_t sh   = (lane & 2) << 2;                       // 0 or 8
    const uint32_t mask = (lane & 1) ? 0x00F000F0u : 0x000F000Fu;
    const uint32_t cm2  = (lane & 1) ? 0x2C002C00u : 0x3C003C00u; // 1/16 : 1.0
    const uint32_t ca2  = (lane & 1) ? 0xD480D480u : 0xE408E408u; // -72 : -1032

    const int ntile = blockIdx.x;
    const int split = blockIdx.y;
    const int nbase = ntile * NTILE;
    const int k0    = split * KSPLIT;
    const int qrow_base = k0 >> 3;         // first qweight row of this split
    const int wc = warp * 32 + lane4;      // in-tile column of this thread's frag rows

    // W tile cp.async coords: 16 rows x 256 int32, 4 x 16B per thread
    const int wr  = tid >> 4;              // 0..15 row
    const int wc4 = tid & 15;              // 16B group
    const int srow0 = split * NUM_KT;

    // ---- prologue: prefetch W/S tiles 0 and 1 ----
#pragma unroll
    for (int p = 0; p < 2; p++) {
        const int* wsrc = qw + (size_t)(qrow_base + p * 16 + wr) * N_DIM + nbase + wc4 * 4;
        uint32_t wdst = smem_u32 + W_OFF + p * W_TILE + wr * 1024 + wc4 * 16;
#pragma unroll
        for (int j = 0; j < 4; j++)
            cpasync16(wdst + j * 256, wsrc + j * 64);
        if (tid < 64)
            cpasync16(smem_u32 + S_OFF + p * S_TILE + tid * 16,
                      scales + (size_t)(srow0 + p) * N_DIM + nbase + tid * 4);
        CP_COMMIT();
    }

    // ---- preload whole A split-slice: fp32 -> fp16 SMEM, k-permuted per octet ----
    // octet values v0..v7 stored as (v0,v4)(v1,v5)(v2,v6)(v3,v7) -> one uint4 store
    {
        const int am = tid >> 3;           // 0..31 m-row
        const int ao = tid & 7;            // octet lane
        const float* arow = A + (size_t)am * K_DIM + k0;
        half* drow = a_sm + (size_t)am * APITCH;
#pragma unroll
        for (int j = 0; j < 8; j++) {
            const int o = ao + 8 * j;      // octet 0..63
            float4 va = *reinterpret_cast<const float4*>(arow + o * 8);
            float4 vb = *reinterpret_cast<const float4*>(arow + o * 8 + 4);
            half2 p0 = __floats2half2_rn(va.x, vb.x);   // (v0, v4)
            half2 p1 = __floats2half2_rn(va.y, vb.y);   // (v1, v5)
            half2 p2 = __floats2half2_rn(va.z, vb.z);   // (v2, v6)
            half2 p3 = __floats2half2_rn(va.w, vb.w);   // (v3, v7)
            uint4 pk;
            pk.x = *reinterpret_cast<uint32_t*>(&p0);
            pk.y = *reinterpret_cast<uint32_t*>(&p1);
            pk.z = *reinterpret_cast<uint32_t*>(&p2);
            pk.w = *reinterpret_cast<uint32_t*>(&p3);
            *reinterpret_cast<uint4*>(drow + o * 8) = pk;
        }
    }

    // Accumulators: [a-frag f(2)][m-tile t(4)][4]
    float acc[2][4][4];
#pragma unroll
    for (int f = 0; f < 2; f++)
#pragma unroll
        for (int t = 0; t < 4; t++)
#pragma unroll
            for (int r = 0; r < 4; r++) acc[f][t][r] = 0.0f;

    CP_WAIT(1);            // tile 0 resident
    __syncthreads();

#pragma unroll 1
    for (int kt = 0; kt < NUM_KT; kt++) {
        const int buf = kt & 1;
        const uint32_t* w_sm = reinterpret_cast<const uint32_t*>(smem + W_OFF + buf * W_TILE);
        const float*    s_sm = reinterpret_cast<const float*>(smem + S_OFF + buf * S_TILE);

        // per-group scales for this thread's 4 n-columns
        uint32_t s2[4];
#pragma unroll
        for (int r = 0; r < 4; r++) {
            half shalf = __float2half_rn(s_sm[wc + 8 * r]);
            half2 p = __halves2half2(shalf, shalf);
            s2[r] = *reinterpret_cast<uint32_t*>(&p);
        }

        // ---- 8 chunks of k16 ----
#pragma unroll
        for (int ch = 0; ch < 8; ch++) {
            const uint32_t* r0 = w_sm + (2 * ch) * 256 + wc;
            const uint32_t* r1 = r0 + 256;
            uint32_t q00 = r0[0],  q01 = r0[8],  q02 = r0[16], q03 = r0[24];
            uint32_t q10 = r1[0],  q11 = r1[8],  q12 = r1[16], q13 = r1[24];

            uint32_t a[2][4];
            a[0][0] = dq2(q00, sh, mask, cm2, ca2, s2[0]);
            a[0][1] = dq2(q01, sh, mask, cm2, ca2, s2[1]);
            a[0][2] = dq2(q10, sh, mask, cm2, ca2, s2[0]);
            a[0][3] = dq2(q11, sh, mask, cm2, ca2, s2[1]);
            a[1][0] = dq2(q02, sh, mask, cm2, ca2, s2[2]);
            a[1][1] = dq2(q03, sh, mask, cm2, ca2, s2[3]);
            a[1][2] = dq2(q12, sh, mask, cm2, ca2, s2[2]);
            a[1][3] = dq2(q13, sh, mask, cm2, ca2, s2[3]);

            // b-frags: permuted-k pairs, m = 8t + lane4, pair j = lane&3
            const half* bb = a_sm + (size_t)(kt * 128 + ch * 16 + (lane & 3) * 2);
            uint32_t b[4][2];
#pragma unroll
            for (int t = 0; t < 4; t++) {
                const half* bp = bb + (size_t)(8 * t + lane4) * APITCH;
                b[t][0] = *reinterpret_cast<const uint32_t*>(bp);
                b[t][1] = *reinterpret_cast<const uint32_t*>(bp + 8);
            }

#pragma unroll
            for (int f = 0; f < 2; f++)
#pragma unroll
                for (int t = 0; t < 4; t++)
                    mma_16816(acc[f][t][0], acc[f][t][1], acc[f][t][2], acc[f][t][3],
                              a[f][0], a[f][1], a[f][2], a[f][3], b[t][0], b[t][1]);
        }

        __syncthreads();                   // all warps done reading W[buf]
        if (kt + 2 < NUM_KT) {
            const int nt = kt + 2;
            const int* wsrc = qw + (size_t)(qrow_base + nt * 16 + wr) * N_DIM + nbase + wc4 * 4;
            uint32_t wdst = smem_u32 + W_OFF + buf * W_TILE + wr * 1024 + wc4 * 16;
#pragma unroll
            for (int j = 0; j < 4; j++)
                cpasync16(wdst + j * 256, wsrc + j * 64);
            if (tid < 64)
                cpasync16(smem_u32 + S_OFF + buf * S_TILE + tid * 16,
                          scales + (size_t)(srow0 + nt) * N_DIM + nbase + tid * 4);
            CP_COMMIT();
            CP_WAIT(1);                    // tile kt+1 resident
        } else {
            CP_WAIT(0);
        }
        __syncthreads();
    }

    // ---- write split partials: D[n][m] frag -> partial[split][m][n] ----
    float* pbase = g_partial + (size_t)split * M_DIM * N_DIM;
#pragma unroll
    for (int f = 0; f < 2; f++) {
        const int n_r = nbase + warp * 32 + 16 * f + lane4;
#pragma unroll
        for (int t = 0; t < 4; t++) {
            const int m_c = 8 * t + 2 * (lane & 3);
            float* p = pbase + (size_t)m_c * N_DIM + n_r;
            p[0]         = acc[f][t][0];
            p[N_DIM]     = acc[f][t][1];
            p[8]         = acc[f][t][2];
            p[N_DIM + 8] = acc[f][t][3];
        }
    }

    // ---- fused reduction: last CTA per n-tile sums all splits + bias ----
    __threadfence();
    __syncthreads();
    if (tid == 0) s_old = atomicAdd(&g_ctr[ntile], 1);
    __syncthreads();

    if (s_old == SPLITS - 1) {
        __threadfence();
        const int n = nbase + tid;         // 256 threads = 256 n-columns
        const float bv = bias[n];
#pragma unroll 4
        for (int m = 0; m < M_DIM; m++) {
            const float* p = g_partial + (size_t)m * N_DIM + n;
            float v = 0.0f;
#pragma unroll
            for (int sp = 0; sp < SPLITS; sp++)
                v += p[(size_t)sp * (M_DIM * N_DIM)];
            out[(size_t)m * N_DIM + n] = v + bv;
        }
        __threadfence();
        if (tid == 0) g_ctr[ntile] = 0;    // reset for next launch
    }
}

extern "C" void kernel_launch(void* const* d_in, const int* in_sizes, int n_in,
                              void* d_out, int out_size) {
    const float* A      = (const float*)d_in[0];
    const int*   qw     = (const int*)d_in[1];
    const float* scales = (const float*)d_in[2];
    const float* bias   = (const float*)d_in[3];
    float* out = (float*)d_out;

    cudaFuncSetAttribute(marlin_w4a16_fused,
                         cudaFuncAttributeMaxDynamicSharedMemorySize, SMEM_TOTAL);
    dim3 grid(NTILES, SPLITS);
    marlin_w4a16_fused<<<grid, THREADS, SMEM_TOTAL>>>(A, qw, scales, bias, out);
}

// round 8
// speedup vs baseline: 1.5085x; 1.5085x over previous
#include <cuda_runtime.h>
#include <cuda_fp16.h>
#include <cstdint>

// Problem constants
#define M_DIM   32
#define K_DIM   8192
#define N_DIM   8192
#define GROUP   128

#define NTILE   256                    // n-columns per CTA
#define SPLITS  8                      // split-K factor
#define KSPLIT  (K_DIM / SPLITS)       // 1024 k per CTA
#define NUM_KT  (KSPLIT / GROUP)       // 8 scale-groups per split
#define NCHUNK  (KSPLIT / 16)          // 64 k16 chunks per split
#define THREADS 256                    // 8 warps, each owns 32 n-columns
#define NTILES  (N_DIM / NTILE)        // 32

// A SMEM: [32 m][APITCH halves], k-permuted per octet (v0,v4,v1,v5,v2,v6,v3,v7)
// row stride 1032*2=2064 B == 16 mod 128 -> b-frag banks 4*lane4+(lane&3): conflict-free
#define APITCH  1032
#define A_BYTES (M_DIM * APITCH * 2)   // 66048

// Split-K partials + completion counters (static device scratch)
__device__ float    g_partial[SPLITS * M_DIM * N_DIM];
__device__ unsigned g_ctr[NTILES];

static __device__ __forceinline__ uint32_t lop3_and_or(uint32_t a, uint32_t b, uint32_t c) {
    uint32_t d;
    asm("lop3.b32 %0, %1, %2, %3, 0xEA;" : "=r"(d) : "r"(a), "r"(b), "r"(c));
    return d;
}

// Uniform per-lane dequant: lane j = lane&3 extracts nibble pair (j, j+4) of qword.
//  j even: h = ((q>>sh) & 0x000F000F) | 0x64006400 ; v = h*1 + (-1032)  = q-8 (exact)
//  j odd:  h = ((q>>sh) & 0x00F000F0) | 0x64006400 ; v = h*(1/16) + (-72) = q-8 (exact)
// then r = v * s (one fp16 rounding).
static __device__ __forceinline__ uint32_t dq2(uint32_t q, uint32_t sh, uint32_t mask,
                                               uint32_t cm2, uint32_t ca2, uint32_t s2) {
    uint32_t u = q >> sh;
    uint32_t h = lop3_and_or(u, mask, 0x64006400u);
    half2 v = __hfma2(*reinterpret_cast<half2*>(&h),
                      *reinterpret_cast<half2*>(&cm2),
                      *reinterpret_cast<half2*>(&ca2));
    half2 r = __hmul2(v, *reinterpret_cast<half2*>(&s2));
    return *reinterpret_cast<uint32_t*>(&r);
}

static __device__ __forceinline__ void mma_16816(float& d0, float& d1, float& d2, float& d3,
                                                 uint32_t a0, uint32_t a1, uint32_t a2,
                                                 uint32_t a3, uint32_t b0, uint32_t b1) {
    asm volatile(
        "mma.sync.aligned.m16n8k16.row.col.f32.f16.f16.f32 "
        "{%0,%1,%2,%3}, {%4,%5,%6,%7}, {%8,%9}, {%0,%1,%2,%3};\n"
        : "+f"(d0), "+f"(d1), "+f"(d2), "+f"(d3)
        : "r"(a0), "r"(a1), "r"(a2), "r"(a3), "r"(b0), "r"(b1));
}

__global__ void __launch_bounds__(THREADS, 2)
marlin_w4a16_fused(const float* __restrict__ A, const int* __restrict__ qw,
                   const float* __restrict__ scales, const float* __restrict__ bias,
                   float* __restrict__ out) {
    extern __shared__ __align__(16) char smem[];
    __shared__ unsigned s_old;
    half* a_sm = reinterpret_cast<half*>(smem);

    const int tid   = threadIdx.x;
    const int lane  = tid & 31;
    const int warp  = tid >> 5;            // 0..7
    const int lane4 = lane >> 2;           // 0..7

    // per-lane dequant constants
    const uint32_t sh   = (lane & 2) << 2;                        // 0 or 8
    const uint32_t mask = (lane & 1) ? 0x00F000F0u : 0x000F000Fu;
    const uint32_t cm2  = (lane & 1) ? 0x2C002C00u : 0x3C003C00u; // 1/16 : 1.0
    const uint32_t ca2  = (lane & 1) ? 0xD480D480u : 0xE408E408u; // -72 : -1032

    const int ntile = blockIdx.x;
    const int split = blockIdx.y;
    const int nbase = ntile * NTILE;
    const int k0    = split * KSPLIT;
    const int wc    = warp * 32 + lane4;   // in-tile column of this thread's frag rows

    // ---- whole-A split-slice preload: fp32 -> fp16, k-permuted octets ----
    {
        const int am = tid >> 3;           // 0..31 m-row
        const int ao = tid & 7;            // 0..7
        const float* arow = A + (size_t)am * K_DIM + k0;
        half* drow = a_sm + (size_t)am * APITCH;
#pragma unroll
        for (int j = 0; j < 16; j++) {
            const int o = ao + 8 * j;      // octet 0..127
            float4 va = *reinterpret_cast<const float4*>(arow + o * 8);
            float4 vb = *reinterpret_cast<const float4*>(arow + o * 8 + 4);
            half2 p0 = __floats2half2_rn(va.x, vb.x);   // (v0, v4)
            half2 p1 = __floats2half2_rn(va.y, vb.y);   // (v1, v5)
            half2 p2 = __floats2half2_rn(va.z, vb.z);   // (v2, v6)
            half2 p3 = __floats2half2_rn(va.w, vb.w);   // (v3, v7)
            uint4 pk;
            pk.x = *reinterpret_cast<uint32_t*>(&p0);
            pk.y = *reinterpret_cast<uint32_t*>(&p1);
            pk.z = *reinterpret_cast<uint32_t*>(&p2);
            pk.w = *reinterpret_cast<uint32_t*>(&p3);
            *reinterpret_cast<uint4*>(drow + o * 8) = pk;
        }
    }

    // Accumulators: [a-frag f(2)][m-tile t(4)][4]
    float acc[2][4][4];
#pragma unroll
    for (int f = 0; f < 2; f++)
#pragma unroll
        for (int t = 0; t < 4; t++)
#pragma unroll
            for (int r = 0; r < 4; r++) acc[f][t][r] = 0.0f;

    // ---- W pointer & prefetch state ----
    // chunk c uses qweight rows (k0/8 + 2c, +2c+1), cols wc + {0,8,16,24}
    const int* qp = qw + (size_t)(k0 >> 3) * N_DIM + nbase + wc;
    const float* sp = scales + (size_t)split * NUM_KT * N_DIM + nbase + wc;

    uint32_t qc[8], qn[8];
    float sraw[4];
    // prefetch chunk 0 qwords
    {
        const int* r0 = qp;
        const int* r1 = qp + N_DIM;
        qc[0] = r0[0];  qc[1] = r0[8];  qc[2] = r0[16]; qc[3] = r0[24];
        qc[4] = r1[0];  qc[5] = r1[8];  qc[6] = r1[16]; qc[7] = r1[24];
    }
    // prefetch kt=0 scales
#pragma unroll
    for (int r = 0; r < 4; r++) sraw[r] = sp[8 * r];

    __syncthreads();       // A tile resident (the only barrier before epilogue)

    uint32_t s2[4];

#pragma unroll 2
    for (int c = 0; c < NCHUNK; c++) {
        // kt boundary: convert prefetched scales, start next kt's scale loads
        if ((c & 7) == 0) {
#pragma unroll
            for (int r = 0; r < 4; r++) {
                half hs = __float2half_rn(sraw[r]);
                half2 p = __halves2half2(hs, hs);
                s2[r] = *reinterpret_cast<uint32_t*>(&p);
            }
            if (c + 8 < NCHUNK) {
                const float* spn = sp + (size_t)((c >> 3) + 1) * N_DIM;
#pragma unroll
                for (int r = 0; r < 4; r++) sraw[r] = spn[8 * r];
            }
        }

        // prefetch next chunk's qwords (overlaps with dequant+MMA below)
        if (c + 1 < NCHUNK) {
            const int* r0 = qp + (size_t)(2 * (c + 1)) * N_DIM;
            const int* r1 = r0 + N_DIM;
            qn[0] = r0[0];  qn[1] = r0[8];  qn[2] = r0[16]; qn[3] = r0[24];
            qn[4] = r1[0];  qn[5] = r1[8];  qn[6] = r1[16]; qn[7] = r1[24];
        }

        // dequant current chunk into a-frags
        uint32_t a[2][4];
        a[0][0] = dq2(qc[0], sh, mask, cm2, ca2, s2[0]);
        a[0][1] = dq2(qc[1], sh, mask, cm2, ca2, s2[1]);
        a[0][2] = dq2(qc[4], sh, mask, cm2, ca2, s2[0]);
        a[0][3] = dq2(qc[5], sh, mask, cm2, ca2, s2[1]);
        a[1][0] = dq2(qc[2], sh, mask, cm2, ca2, s2[2]);
        a[1][1] = dq2(qc[3], sh, mask, cm2, ca2, s2[3]);
        a[1][2] = dq2(qc[6], sh, mask, cm2, ca2, s2[2]);
        a[1][3] = dq2(qc[7], sh, mask, cm2, ca2, s2[3]);

        // b-frags: permuted-k pairs, m = 8t + lane4, pair j = lane&3
        const half* bb = a_sm + (size_t)(c * 16 + (lane & 3) * 2);
        uint32_t b[4][2];
#pragma unroll
        for (int t = 0; t < 4; t++) {
            const half* bp = bb + (size_t)(8 * t + lane4) * APITCH;
            b[t][0] = *reinterpret_cast<const uint32_t*>(bp);
            b[t][1] = *reinterpret_cast<const uint32_t*>(bp + 8);
        }

#pragma unroll
        for (int f = 0; f < 2; f++)
#pragma unroll
            for (int t = 0; t < 4; t++)
                mma_16816(acc[f][t][0], acc[f][t][1], acc[f][t][2], acc[f][t][3],
                          a[f][0], a[f][1], a[f][2], a[f][3], b[t][0], b[t][1]);

#pragma unroll
        for (int i = 0; i < 8; i++) qc[i] = qn[i];
    }

    // ---- write split partials: D[n][m] frag -> partial[split][m][n] ----
    float* pbase = g_partial + (size_t)split * M_DIM * N_DIM;
#pragma unroll
    for (int f = 0; f < 2; f++) {
        const int n_r = nbase + warp * 32 + 16 * f + lane4;
#pragma unroll
        for (int t = 0; t < 4; t++) {
            const int m_c = 8 * t + 2 * (lane & 3);
            float* p = pbase + (size_t)m_c * N_DIM + n_r;
            p[0]         = acc[f][t][0];
            p[N_DIM]     = acc[f][t][1];
            p[8]         = acc[f][t][2];
            p[N_DIM + 8] = acc[f][t][3];
        }
    }

    // ---- fused reduction: last CTA per n-tile sums all splits + bias ----
    __threadfence();
    __syncthreads();
    if (tid == 0) s_old = atomicAdd(&g_ctr[ntile], 1);
    __syncthreads();

    if (s_old == SPLITS - 1) {
        __threadfence();
        const int n = nbase + tid;         // 256 threads = 256 n-columns
        const float bv = bias[n];
#pragma unroll 4
        for (int m = 0; m < M_DIM; m++) {
            const float* p = g_partial + (size_t)m * N_DIM + n;
            float v = 0.0f;
#pragma unroll
            for (int sp2 = 0; sp2 < SPLITS; sp2++)
                v += p[(size_t)sp2 * (M_DIM * N_DIM)];
            out[(size_t)m * N_DIM + n] = v + bv;
        }
        __threadfence();
        if (tid == 0) g_ctr[ntile] = 0;    // reset for next launch
    }
}

extern "C" void kernel_launch(void* const* d_in, const int* in_sizes, int n_in,
                              void* d_out, int out_size) {
    const float* A      = (const float*)d_in[0];
    const int*   qw     = (const int*)d_in[1];
    const float* scales = (const float*)d_in[2];
    const float* bias   = (const float*)d_in[3];
    float* out = (float*)d_out;

    cudaFuncSetAttribute(marlin_w4a16_fused,
                         cudaFuncAttributeMaxDynamicSharedMemorySize, A_BYTES);
    dim3 grid(NTILES, SPLITS);
    marlin_w4a16_fused<<<grid, THREADS, A_BYTES>>>(A, qw, scales, bias, out);
}